// round 3
// baseline (speedup 1.0000x reference)
#include <cuda_runtime.h>

// SkelConv, f32x2 FMA with parity-split pair operands (sm_103a).
// Even-parity x pairs come directly from aligned LDG.128 (zero pack cost);
// only 9 odd-parity pairs per ci are packed. Weights duplicated {w,w} in SMEM.

#define C_IN   103
#define C_OUT  206
#define KK     15
#define TLEN   8192
#define NB     32
#define U      4
#define TPB    128
#define TT     (TPB * U)   // 512
#define OW     8

typedef unsigned long long u64;

__device__ __forceinline__ u64 pack2(float lo, float hi) {
    u64 r;
    asm("mov.b64 %0, {%1, %2};" : "=l"(r) : "f"(lo), "f"(hi));
    return r;
}
__device__ __forceinline__ void unpack2(u64 v, float& lo, float& hi) {
    asm("mov.b64 {%0, %1}, %2;" : "=f"(lo), "=f"(hi) : "l"(v));
}
__device__ __forceinline__ void ffma2(u64& d, u64 a, u64 b) {
    asm("fma.rn.f32x2 %0, %1, %2, %0;" : "+l"(d) : "l"(a), "l"(b));
}
// xo = {hi(a), lo(b)}
__device__ __forceinline__ u64 mkodd(u64 a, u64 b) {
    float alo, ahi, blo, bhi;
    unpack2(a, alo, ahi);
    unpack2(b, blo, bhi);
    return pack2(ahi, blo);
}

// y = 0..25: 0,1 = root halves (7 out ch each), y>=2 -> joint j=y-1 (8 out ch)
__device__ __forceinline__ void jp(int y, int& i0, int& iw, int& o0, int& ow) {
    if (y == 0)      { i0 = 0;  iw = 11; o0 = 0; ow = 7; }
    else if (y == 1) { i0 = 0;  iw = 11; o0 = 7; ow = 7; }
    else {
        const int j = y - 1;
        o0 = 14 + (j - 1) * 8; ow = 8;
        if (j == 1)       { i0 = 0;              iw = 15; }
        else if (j == 24) { i0 = 95;             iw = 8;  }
        else              { i0 = 7 + (j - 2) * 4; iw = 12; }
    }
}

__global__ void __launch_bounds__(TPB)
skel_conv3_kernel(const float* __restrict__ x,
                  const float* __restrict__ w,
                  const float* __restrict__ bias,
                  const float* __restrict__ mask,
                  float* __restrict__ out)
{
    int i0, iw, o0, ow;
    jp(blockIdx.y, i0, iw, o0, ow);

    const int b   = blockIdx.z;
    const int tid = threadIdx.x;
    const int t0  = blockIdx.x * TT + tid * U;

    // Masked weights, duplicated {w,w}, K padded to 16 pairs (128b LDS rows).
    __shared__ float2 wsh[OW][15][16];
    {
        const int total = OW * iw * 16;
        for (int idx = tid; idx < total; idx += TPB) {
            const int k  = idx & 15;
            const int r  = idx >> 4;
            const int ci = r % iw;
            const int co = r / iw;
            float v = 0.0f;
            if (k < KK && co < ow) {
                const int gi = ((o0 + co) * C_IN + (i0 + ci)) * KK + k;
                v = w[gi] * mask[gi];
            }
            wsh[co][ci][k] = make_float2(v, v);
        }
    }
    __syncthreads();

    u64 acc01[OW], acc23[OW];
#pragma unroll
    for (int co = 0; co < OW; co++) { acc01[co] = 0ull; acc23[co] = 0ull; }

    const bool interior = (blockIdx.x > 0) && (blockIdx.x + 1 < gridDim.x);
    const float* xb = x + (size_t)b * C_IN * TLEN;

    for (int ci = 0; ci < iw; ci++) {
        const float* xrow = xb + (size_t)(i0 + ci) * TLEN;

        // Window x[t0-8 .. t0+11]; xe[i] = {x[t0-8+2i], x[t0-8+2i+1]}.
        u64 xe[10];
        if (interior) {
            const ulonglong2* xq =
                reinterpret_cast<const ulonglong2*>(xrow + t0 - 8);
#pragma unroll
            for (int q = 0; q < 5; q++) {
                const ulonglong2 v = xq[q];
                xe[2 * q]     = v.x;
                xe[2 * q + 1] = v.y;
            }
        } else {
            float xr[20];
#pragma unroll
            for (int m = 0; m < 20; m++) {
                const int t = t0 - 8 + m;
                xr[m] = (t >= 0 && t < TLEN) ? xrow[t] : 0.0f;
            }
#pragma unroll
            for (int i = 0; i < 10; i++) xe[i] = pack2(xr[2 * i], xr[2 * i + 1]);
        }

        // Odd-parity pairs: xo[i] = {x[t0-7+2i], x[t0-6+2i]}, i = 0..8.
        u64 xo[9];
#pragma unroll
        for (int i = 0; i < 9; i++) xo[i] = mkodd(xe[i], xe[i + 1]);

#pragma unroll
        for (int co = 0; co < OW; co++) {
            const ulonglong2* wq =
                reinterpret_cast<const ulonglong2*>(&wsh[co][ci][0]);
#pragma unroll
            for (int q = 0; q < 8; q++) {
                const ulonglong2 v = wq[q];   // weight pairs for k=2q, 2q+1
                // even tap k = 2q: acc01 pair starts odd -> xo[q], xo[q+1]
                ffma2(acc01[co], v.x, xo[q]);
                ffma2(acc23[co], v.x, xo[q + 1]);
                // odd tap k = 2q+1 (skip k=15): pair starts even -> xe
                if (2 * q + 1 < KK) {
                    ffma2(acc01[co], v.y, xe[q + 1]);
                    ffma2(acc23[co], v.y, xe[q + 2]);
                }
            }
        }
    }

    float* ob = out + (size_t)b * C_OUT * TLEN + t0;
#pragma unroll
    for (int co = 0; co < OW; co++) {
        if (co < ow) {
            const float bv = bias[o0 + co];
            float4 r;
            unpack2(acc01[co], r.x, r.y);
            unpack2(acc23[co], r.z, r.w);
            r.x += bv; r.y += bv; r.z += bv; r.w += bv;
            *reinterpret_cast<float4*>(ob + (size_t)(o0 + co) * TLEN) = r;
        }
    }
}

extern "C" void kernel_launch(void* const* d_in, const int* in_sizes, int n_in,
                              void* d_out, int out_size)
{
    (void)in_sizes; (void)n_in; (void)out_size;
    const float* x    = (const float*)d_in[0];
    const float* w    = (const float*)d_in[1];
    const float* bias = (const float*)d_in[2];
    const float* mask = (const float*)d_in[3];
    float* out = (float*)d_out;

    dim3 grid(TLEN / TT, 26, NB);
    skel_conv3_kernel<<<grid, TPB>>>(x, w, bias, mask, out);
}